// round 4
// baseline (speedup 1.0000x reference)
#include <cuda_runtime.h>

// Problem constants
#define BB 8
#define NN 5000
#define EE 40000
#define FF 64
#define FEE 16
#define FIL 96
#define BN (BB*NN)      // 40000
#define BE (BB*EE)      // 320000
#define UPD_ELEMS (BN*FIL)   // 3,840,000
#define MSG_ELEMS (BE*FIL)   // 30,720,000
#define LN_EPS 1e-3f

// Scratch (device globals: allocation-free per harness rules)
__device__ float g_Pa[UPD_ELEMS];   // nodes @ Wm[0:64]
__device__ float g_Pb[UPD_ELEMS];   // nodes @ Wm[64:128]
__device__ float g_agg[UPD_ELEMS];  // segment-sum of messages

__device__ __forceinline__ float warp_sum(float v) {
#pragma unroll
    for (int o = 16; o; o >>= 1) v += __shfl_xor_sync(0xffffffffu, v, o);
    return v;
}

// ---------------------------------------------------------------------------
// K0: zero aggregation buffer. 3,840,000 = 3750 * 1024 exactly.
// ---------------------------------------------------------------------------
__global__ void zero_agg_kernel() {
    int i = blockIdx.x * 1024 + threadIdx.x;
    g_agg[i] = 0.0f;
}

// ---------------------------------------------------------------------------
// K1: Pa|Pb = nodes(40000x64) @ [Wm[0:64] | Wm[64:128]] (64x192)
// 64-row tile per block, 256 threads, 8x6 micro-tile per thread, K tiled by 32.
// ---------------------------------------------------------------------------
__global__ __launch_bounds__(256) void precompute_kernel(
    const float* __restrict__ nodes, const float* __restrict__ Wm) {
    __shared__ float Xs[64][32];
    __shared__ float Ws[32][192];

    int tid = threadIdx.x;
    int tx = tid & 31, ty = tid >> 5;
    int row0 = blockIdx.x * 64;

    float acc[8][6];
#pragma unroll
    for (int i = 0; i < 8; i++)
#pragma unroll
        for (int j = 0; j < 6; j++) acc[i][j] = 0.0f;

    for (int t = 0; t < 2; t++) {
        __syncthreads();
        // W tile: 32x192 = 6144 floats, 24 per thread.
        // Column c<96 -> Wm row (t*32+k); c>=96 -> Wm row (64+t*32+k), col c-96.
#pragma unroll
        for (int it = 0; it < 24; it++) {
            int idx = tid + 256 * it;
            int k = idx / 192, c = idx % 192;
            float v = (c < 96) ? Wm[(t * 32 + k) * FIL + c]
                               : Wm[(64 + t * 32 + k) * FIL + (c - 96)];
            Ws[k][c] = v;
        }
        // X tile: 64 rows x 32 k = 2048 floats, 8 per thread (coalesced).
#pragma unroll
        for (int it = 0; it < 8; it++) {
            int idx = tid + 256 * it;
            int r = idx >> 5, c = idx & 31;
            Xs[r][c] = nodes[(row0 + r) * FF + t * 32 + c];
        }
        __syncthreads();
#pragma unroll
        for (int k = 0; k < 32; k++) {
            float xv[8], wv[6];
#pragma unroll
            for (int i = 0; i < 8; i++) xv[i] = Xs[ty + 8 * i][k];   // broadcast
#pragma unroll
            for (int j = 0; j < 6; j++) wv[j] = Ws[k][tx + 32 * j];  // conflict-free
#pragma unroll
            for (int i = 0; i < 8; i++)
#pragma unroll
                for (int j = 0; j < 6; j++) acc[i][j] += xv[i] * wv[j];
        }
    }

#pragma unroll
    for (int i = 0; i < 8; i++) {
        int row = row0 + ty + 8 * i;
#pragma unroll
        for (int j = 0; j < 6; j++) {
            int c = tx + 32 * j;
            if (c < 96) g_Pa[row * FIL + c] = acc[i][j];
            else        g_Pb[row * FIL + (c - 96)] = acc[i][j];
        }
    }
}

// ---------------------------------------------------------------------------
// K2: per-edge message = LN(relu(Pa[src] + Pb[dst] + ef@WmC + bm)),
// write messages, atomicAdd into g_agg[dst]. One warp per edge, 8 edges/block.
// ---------------------------------------------------------------------------
__global__ __launch_bounds__(256) void edge_kernel(
    const float* __restrict__ ef, const int* __restrict__ edges,
    const float* __restrict__ Wm, const float* __restrict__ bm,
    const float* __restrict__ gamma, const float* __restrict__ beta,
    float* __restrict__ msg_out, int write_msg) {
    __shared__ float WmC[16 * 96];  // Wm rows 128..143
    __shared__ float s_bm[96], s_g[96], s_b[96];

    int tid = threadIdx.x;
    for (int i = tid; i < 16 * 96; i += 256) WmC[i] = Wm[128 * FIL + i];
    if (tid < 96) { s_bm[tid] = bm[tid]; s_g[tid] = gamma[tid]; s_b[tid] = beta[tid]; }
    __syncthreads();

    int warp = tid >> 5, lane = tid & 31;
    int eidx = blockIdx.x * 8 + warp;  // BE = 320000, divisible by 8

    int b = eidx / EE;
    int2 e2 = ((const int2*)edges)[eidx];
    int src = e2.x, dst = e2.y;

    float efv = (lane < 16) ? ef[eidx * FEE + lane] : 0.0f;

    float a0 = s_bm[lane], a1 = s_bm[lane + 32], a2 = s_bm[lane + 64];
#pragma unroll
    for (int k = 0; k < 16; k++) {
        float x = __shfl_sync(0xffffffffu, efv, k);
        a0 += x * WmC[k * 96 + lane];
        a1 += x * WmC[k * 96 + lane + 32];
        a2 += x * WmC[k * 96 + lane + 64];
    }

    int pa_off = (b * NN + src) * FIL;
    int pb_off = (b * NN + dst) * FIL;
    a0 += g_Pa[pa_off + lane]      + g_Pb[pb_off + lane];
    a1 += g_Pa[pa_off + lane + 32] + g_Pb[pb_off + lane + 32];
    a2 += g_Pa[pa_off + lane + 64] + g_Pb[pb_off + lane + 64];

    // relu
    a0 = fmaxf(a0, 0.0f); a1 = fmaxf(a1, 0.0f); a2 = fmaxf(a2, 0.0f);

    // LayerNorm over 96 (warp-level)
    float mean = warp_sum(a0 + a1 + a2) * (1.0f / 96.0f);
    float d0 = a0 - mean, d1 = a1 - mean, d2 = a2 - mean;
    float var = warp_sum(d0 * d0 + d1 * d1 + d2 * d2) * (1.0f / 96.0f);
    float inv = rsqrtf(var + LN_EPS);
    float y0 = d0 * inv * s_g[lane]      + s_b[lane];
    float y1 = d1 * inv * s_g[lane + 32] + s_b[lane + 32];
    float y2 = d2 * inv * s_g[lane + 64] + s_b[lane + 64];

    if (write_msg) {
        int mo = eidx * FIL;
        msg_out[mo + lane]      = y0;
        msg_out[mo + lane + 32] = y1;
        msg_out[mo + lane + 64] = y2;
    }
    // aggregate on destination node (edges[...,1] == dst)
    atomicAdd(&g_agg[pb_off + lane],      y0);
    atomicAdd(&g_agg[pb_off + lane + 32], y1);
    atomicAdd(&g_agg[pb_off + lane + 64], y2);
}

// ---------------------------------------------------------------------------
// K3: updated = LN(relu([nodes | agg](40000x160) @ Wu(160x96) + bu))
// 64-row tile per block, 256 threads, 8x3 micro-tile, K tiled by 32 (5 tiles),
// fused ReLU + LayerNorm epilogue (warp owns complete rows).
// ---------------------------------------------------------------------------
__global__ __launch_bounds__(256) void update_kernel(
    const float* __restrict__ nodes, const float* __restrict__ Wu,
    const float* __restrict__ bu, const float* __restrict__ gamma,
    const float* __restrict__ beta, float* __restrict__ out) {
    __shared__ float Xs[64][32];
    __shared__ float Ws[32][96];
    __shared__ float s_bu[96], s_g[96], s_b[96];

    int tid = threadIdx.x;
    int tx = tid & 31, ty = tid >> 5;
    int row0 = blockIdx.x * 64;

    if (tid < 96) { s_bu[tid] = bu[tid]; s_g[tid] = gamma[tid]; s_b[tid] = beta[tid]; }
    __syncthreads();

    float acc[8][3];
#pragma unroll
    for (int i = 0; i < 8; i++) {
        acc[i][0] = s_bu[tx];
        acc[i][1] = s_bu[tx + 32];
        acc[i][2] = s_bu[tx + 64];
    }

    for (int t = 0; t < 5; t++) {
        __syncthreads();
        // W tile: 32x96 = 3072 floats, 12 per thread.
#pragma unroll
        for (int it = 0; it < 12; it++) {
            int idx = tid + 256 * it;
            int k = idx / 96, c = idx % 96;
            Ws[k][c] = Wu[(t * 32 + k) * FIL + c];
        }
        // X tile: first 64 K-cols from nodes, remaining 96 from g_agg.
#pragma unroll
        for (int it = 0; it < 8; it++) {
            int idx = tid + 256 * it;
            int r = idx >> 5, c = idx & 31;
            float v;
            if (t < 2) v = nodes[(row0 + r) * FF + t * 32 + c];
            else       v = g_agg[(row0 + r) * FIL + (t - 2) * 32 + c];
            Xs[r][c] = v;
        }
        __syncthreads();
#pragma unroll
        for (int k = 0; k < 32; k++) {
            float xv[8];
#pragma unroll
            for (int i = 0; i < 8; i++) xv[i] = Xs[ty + 8 * i][k];
            float w0 = Ws[k][tx], w1 = Ws[k][tx + 32], w2 = Ws[k][tx + 64];
#pragma unroll
            for (int i = 0; i < 8; i++) {
                acc[i][0] += xv[i] * w0;
                acc[i][1] += xv[i] * w1;
                acc[i][2] += xv[i] * w2;
            }
        }
    }

    // Fused ReLU + LayerNorm epilogue; warp = ty owns rows {ty+8i} completely.
#pragma unroll
    for (int i = 0; i < 8; i++) {
        int row = row0 + ty + 8 * i;
        float v0 = fmaxf(acc[i][0], 0.0f);
        float v1 = fmaxf(acc[i][1], 0.0f);
        float v2 = fmaxf(acc[i][2], 0.0f);
        float mean = warp_sum(v0 + v1 + v2) * (1.0f / 96.0f);
        float d0 = v0 - mean, d1 = v1 - mean, d2 = v2 - mean;
        float var = warp_sum(d0 * d0 + d1 * d1 + d2 * d2) * (1.0f / 96.0f);
        float inv = rsqrtf(var + LN_EPS);
        int o = row * FIL;
        out[o + tx]      = d0 * inv * s_g[tx]      + s_b[tx];
        out[o + tx + 32] = d1 * inv * s_g[tx + 32] + s_b[tx + 32];
        out[o + tx + 64] = d2 * inv * s_g[tx + 64] + s_b[tx + 64];
    }
}

// ---------------------------------------------------------------------------
// Launch: zero agg -> precompute Pa/Pb -> edge msg+LN+scatter -> node update.
// ---------------------------------------------------------------------------
extern "C" void kernel_launch(void* const* d_in, const int* in_sizes, int n_in,
                              void* d_out, int out_size) {
    const float* nodes = (const float*)d_in[0];
    const float* ef    = (const float*)d_in[1];
    const int*   edges = (const int*)d_in[2];
    const float* Wm    = (const float*)d_in[3];
    const float* bm    = (const float*)d_in[4];
    const float* ln_mg = (const float*)d_in[5];
    const float* ln_mb = (const float*)d_in[6];
    const float* Wu    = (const float*)d_in[7];
    const float* bu    = (const float*)d_in[8];
    const float* ln_ug = (const float*)d_in[9];
    const float* ln_ub = (const float*)d_in[10];

    float* out = (float*)d_out;
    float* upd_out = out;                  // updated_nodes first (tuple order)
    float* msg_out = out + UPD_ELEMS;      // then messages
    int write_msg = (out_size >= (UPD_ELEMS + MSG_ELEMS)) ? 1 : 0;
    if (!write_msg) msg_out = out;         // harmless placeholder, never stored

    zero_agg_kernel<<<UPD_ELEMS / 1024, 1024>>>();
    precompute_kernel<<<BN / 64, 256>>>(nodes, Wm);
    edge_kernel<<<BE / 8, 256>>>(ef, edges, Wm, bm, ln_mg, ln_mb, msg_out, write_msg);
    update_kernel<<<BN / 64, 256>>>(nodes, Wu, bu, ln_ug, ln_ub, upd_out);
}